// round 11
// baseline (speedup 1.0000x reference)
#include <cuda_runtime.h>
#include <cuda_fp16.h>
#include <math.h>

// Problem constants
#define B_   2
#define HH   56
#define WW   56
#define C_   256
#define NH   8
#define HD   32
#define TOK  (B_*HH*WW)      // 6272
#define POS  (HH*WW)         // 3136
#define QSCALE 0.17677669529663687f

__device__ float g_q[B_*NH*POS*HD];
__device__ float g_k[B_*NH*POS*HD];
__device__ float g_v[B_*NH*POS*HD];
__device__ float g_att[TOK*C_];

__device__ __forceinline__ unsigned f2tf32(float f) {
    unsigned u;
    asm("cvt.rna.tf32.f32 %0, %1;" : "=r"(u) : "f"(f));
    return u;
}
__device__ __forceinline__ unsigned u2tf32(unsigned raw) {
    return f2tf32(__uint_as_float(raw));
}

// ---------------------------------------------------------------------------
// tf32 GEMM, cp.async 3-stage, raw-fp32 smem + fragment-side rna cvt.
// Tile BM x BN, BK=16, 256 threads.
//   qkv : BM=128, BN=128, warps 4x2 (MT=2, NT=8)
//   proj: BM=64,  BN=64,  warps 2x4 (MT=2, NT=2)
// ---------------------------------------------------------------------------
#define ASTR 20
#define NKT  16

__device__ __forceinline__ void cp_async16(unsigned saddr, const void* g) {
    asm volatile("cp.async.ca.shared.global [%0], [%1], 16;"
                 :: "r"(saddr), "l"(g));
}

template<int BM, int BN, int WMW>
__global__ __launch_bounds__(256) void gemm_tf32_kernel(
    const float* __restrict__ A, const float* __restrict__ Bw,
    const float* __restrict__ bias, float* __restrict__ Cout,
    int N, int mode)
{
    constexpr int WNW = 8 / WMW;
    constexpr int NT  = BN / (WNW * 8);
    constexpr int MT  = BM / (WMW * 16);
    constexpr int BSTR = BN + 8;
    constexpr int A_WORDS = BM * ASTR;
    constexpr int B_WORDS = 16 * BSTR;
    constexpr int STAGE_WORDS = A_WORDS + B_WORDS;
    constexpr int ALOADS = BM / 64;            // uint4 A loads/thread
    constexpr int BLOADS = (16*BN/4) / 256;    // uint4 B loads/thread

    extern __shared__ unsigned dsmem[];
    const unsigned sbase = (unsigned)__cvta_generic_to_shared(dsmem);

    const float* __restrict__ Ap = A ? A : g_att;

    const int tid  = threadIdx.x;
    const int lane = tid & 31;
    const int w    = tid >> 5;
    const int wm   = w / WNW;
    const int wn   = w % WNW;
    const int g    = lane >> 2;
    const int tg   = lane & 3;

    const int row0 = blockIdx.y * BM;
    const int col0 = blockIdx.x * BN;

    const int a_r0 = tid >> 2,  a_c0 = (tid & 3) << 2;
    // B load coords depend on BN
    const int b_r0 = (BN == 128) ? (tid >> 5) : (tid >> 4);
    const int b_c0 = (BN == 128) ? ((tid & 31) << 2) : ((tid & 15) << 2);

    float c[MT][NT][4];
    #pragma unroll
    for (int mt = 0; mt < MT; mt++)
        #pragma unroll
        for (int nt = 0; nt < NT; nt++)
            #pragma unroll
            for (int i = 0; i < 4; i++)
                c[mt][nt][i] = 0.0f;

    auto issue_tile = [&](int kt, int st) {
        int k0 = kt * 16;
        unsigned ab = sbase + st*STAGE_WORDS*4;
        #pragma unroll
        for (int ld = 0; ld < ALOADS; ld++) {
            int r = a_r0 + ld*64;
            cp_async16(ab + (r*ASTR + a_c0)*4,
                       &Ap[(long)(row0 + r)*256 + k0 + a_c0]);
        }
        unsigned bb = ab + A_WORDS*4;
        #pragma unroll
        for (int ld = 0; ld < BLOADS; ld++) {
            int r = b_r0 + ld*8;
            cp_async16(bb + (r*BSTR + b_c0)*4,
                       &Bw[(long)(k0 + r)*N + col0 + b_c0]);
        }
        asm volatile("cp.async.commit_group;");
    };

    issue_tile(0, 0);
    issue_tile(1, 1);

    for (int kt = 0; kt < NKT; kt++) {
        if (kt + 1 < NKT)
            asm volatile("cp.async.wait_group 1;" ::: "memory");
        else
            asm volatile("cp.async.wait_group 0;" ::: "memory");
        __syncthreads();

        const unsigned* As = dsmem + (kt % 3)*STAGE_WORDS;
        const unsigned* Bs = As + A_WORDS;

        #pragma unroll
        for (int kc = 0; kc < 16; kc += 8) {
            unsigned a[MT][4], bf[NT][2];
            #pragma unroll
            for (int mt = 0; mt < MT; mt++) {
                int rb = wm*(MT*16) + mt*16;
                a[mt][0] = u2tf32(As[(rb + g    )*ASTR + kc + tg    ]);
                a[mt][1] = u2tf32(As[(rb + g + 8)*ASTR + kc + tg    ]);
                a[mt][2] = u2tf32(As[(rb + g    )*ASTR + kc + tg + 4]);
                a[mt][3] = u2tf32(As[(rb + g + 8)*ASTR + kc + tg + 4]);
            }
            #pragma unroll
            for (int nt = 0; nt < NT; nt++) {
                int cb = wn*(NT*8) + nt*8;
                bf[nt][0] = u2tf32(Bs[(kc + tg    )*BSTR + cb + g]);
                bf[nt][1] = u2tf32(Bs[(kc + tg + 4)*BSTR + cb + g]);
            }
            #pragma unroll
            for (int mt = 0; mt < MT; mt++)
                #pragma unroll
                for (int nt = 0; nt < NT; nt++)
                    asm volatile(
                        "mma.sync.aligned.m16n8k8.row.col.f32.tf32.tf32.f32 "
                        "{%0,%1,%2,%3}, {%4,%5,%6,%7}, {%8,%9}, {%0,%1,%2,%3};"
                        : "+f"(c[mt][nt][0]), "+f"(c[mt][nt][1]),
                          "+f"(c[mt][nt][2]), "+f"(c[mt][nt][3])
                        : "r"(a[mt][0]), "r"(a[mt][1]), "r"(a[mt][2]), "r"(a[mt][3]),
                          "r"(bf[nt][0]), "r"(bf[nt][1]));
        }

        if (kt + 2 < NKT)
            issue_tile(kt + 2, (kt + 2) % 3);
    }

    // Epilogue
    #pragma unroll
    for (int mt = 0; mt < MT; mt++) {
        int r_lo = row0 + wm*(MT*16) + mt*16 + g;
        int r_hi = r_lo + 8;
        #pragma unroll
        for (int nt = 0; nt < NT; nt++) {
            int gj = col0 + wn*(NT*8) + nt*8 + 2*tg;
            float b0 = bias[gj], b1 = bias[gj+1];
            if (mode == 1) {
                Cout[(long)r_lo*N + gj    ] = c[mt][nt][0] + b0;
                Cout[(long)r_lo*N + gj + 1] = c[mt][nt][1] + b1;
                Cout[(long)r_hi*N + gj    ] = c[mt][nt][2] + b0;
                Cout[(long)r_hi*N + gj + 1] = c[mt][nt][3] + b1;
            } else {
                int t = gj >> 8;
                int h = (gj >> 5) & 7;
                int d = gj & 31;
                #pragma unroll
                for (int e = 0; e < 4; e++) {
                    int gm = (e < 2) ? r_lo : r_hi;
                    float v = c[mt][nt][e] + ((e & 1) ? b1 : b0);
                    int bb  = gm / POS;
                    int pos = gm % POS;
                    long off = ((long)(bb*NH + h)*POS + pos)*HD + d + (e & 1);
                    if (t == 0)       g_q[off] = v * QSCALE;
                    else if (t == 1)  g_k[off] = v;
                    else              g_v[off] = v;
                }
            }
        }
    }
}

// ---------------------------------------------------------------------------
// Neighborhood attention: fp16 K/V smem, fp32 Q/accum. 224 threads = 7 warps,
// exactly 7 query rounds (no straggler round).
// ---------------------------------------------------------------------------
#define HALO 13
#define NROW (HALO*HALO)   // 169
#define KSU  20
#define VSU  18
#define NTHR 224

__global__ __launch_bounds__(NTHR) void natten_kernel(const float* __restrict__ rpb0,
                                                      const float* __restrict__ rpb1)
{
    __shared__ alignas(16) unsigned Ksh[NROW*KSU];
    __shared__ alignas(16) unsigned Vsh[NROW*VSU];
    __shared__ alignas(16) float    Qs[49*HD];
    __shared__ alignas(16) float    Ps[7*52];
    __shared__ alignas(16) float    Rs[NROW];
    __shared__ int noff_s[52];

    const int b = blockIdx.z;
    const int h = blockIdx.y;
    const int dil = (h < 4) ? 1 : 2;
    const float* __restrict__ rpb = (h < 4) ? (rpb0 + h*NROW) : (rpb1 + (h-4)*NROW);

    int ry, rx, qy0, qx0, L;
    if (dil == 1) {
        L = 56; ry = 0; rx = 0;
        qy0 = (blockIdx.x >> 3) * 7;
        qx0 = (blockIdx.x & 7) * 7;
    } else {
        L = 28;
        int sub = blockIdx.x >> 4;
        ry = sub >> 1; rx = sub & 1;
        int ti = blockIdx.x & 15;
        qy0 = (ti >> 2) * 7;
        qx0 = (ti & 3) * 7;
    }

    int hy0 = qy0 - 3; if (hy0 < 0) hy0 = 0; if (hy0 > L - HALO) hy0 = L - HALO;
    int hx0 = qx0 - 3; if (hx0 < 0) hx0 = 0; if (hx0 > L - HALO) hx0 = L - HALO;

    const long base = ((long)(b*NH + h)) * POS * HD;
    const int tid = threadIdx.x;

    for (int item = tid; item < NROW*8; item += NTHR) {
        int t  = item >> 3;
        int c  = (item & 7) * 4;
        int iy = t / HALO, ix = t % HALO;
        int gy = (hy0 + iy)*dil + ry;
        int gx = (hx0 + ix)*dil + rx;
        long off = base + (long)(gy*WW + gx)*HD + c;
        float4 kv = *(const float4*)&g_k[off];
        __half2 k01 = __floats2half2_rn(kv.x, kv.y);
        __half2 k23 = __floats2half2_rn(kv.z, kv.w);
        uint2 ku;
        ku.x = *(unsigned*)&k01;  ku.y = *(unsigned*)&k23;
        *(uint2*)&Ksh[t*KSU + (c >> 1)] = ku;
        float4 vv = *(const float4*)&g_v[off];
        __half2 v01 = __floats2half2_rn(vv.x, vv.y);
        __half2 v23 = __floats2half2_rn(vv.z, vv.w);
        uint2 vu;
        vu.x = *(unsigned*)&v01;  vu.y = *(unsigned*)&v23;
        *(uint2*)&Vsh[t*VSU + (c >> 1)] = vu;
    }
    for (int item = tid; item < 49*8; item += NTHR) {
        int q = item >> 3;
        int c = (item & 7) * 4;
        int gy = (qy0 + q/7)*dil + ry;
        int gx = (qx0 + q%7)*dil + rx;
        *(float4*)&Qs[q*HD + c] =
            *(const float4*)&g_q[base + (long)(gy*WW + gx)*HD + c];
    }
    for (int t = tid; t < NROW; t += NTHR) Rs[t] = rpb[t];
    for (int i = tid; i < 52; i += NTHR)
        noff_s[i] = (i < 49) ? (i/7)*HALO + (i%7) : 0;
    __syncthreads();

    const int w    = tid >> 5;          // 0..6
    const int lane = tid & 31;

    if (lane < 3) Ps[w*52 + 49 + lane] = 0.0f;

    const int n1 = lane;
    const int i1 = n1 / 7, j1 = n1 % 7;
    const bool has2 = (lane < 17);
    const int n2 = 32 + lane;
    const int i2 = has2 ? n2 / 7 : 0;
    const int j2 = has2 ? n2 % 7 : 0;
    const int c1 = i1*HALO + j1;
    const int c2 = i2*HALO + j2;

    const int pair = lane >> 4;
    const int dpos = lane & 15;

    #pragma unroll
    for (int t = 0; t < 7; t++) {
        int q = w*7 + t;                 // 7 queries per warp, contiguous
        int qy = qy0 + q / 7;
        int qx = qx0 + q % 7;

        int wsy = qy - 3; if (wsy < 0) wsy = 0; if (wsy > L-7) wsy = L-7;
        int wsx = qx - 3; if (wsx < 0) wsx = 0; if (wsx > L-7) wsx = L-7;
        int oy = wsy - hy0, ox = wsx - hx0;
        int robase = oy*HALO + ox;
        int biy = wsy - qy + 6, bix = wsx - qx + 6;

        const unsigned* k1 = &Ksh[(robase + c1) * KSU];
        const unsigned* k2 = &Ksh[(robase + c2) * KSU];
        const float* qp = &Qs[q*HD];

        float a1 = 0.0f, a2 = 0.0f;
        #pragma unroll
        for (int u = 0; u < 4; u++) {
            float4 q0 = *(const float4*)&qp[u*8];
            float4 q1 = *(const float4*)&qp[u*8 + 4];
            uint4 kk = *(const uint4*)&k1[u*4];
            float2 f;
            f = __half22float2(*(__half2*)&kk.x); a1 += q0.x*f.x + q0.y*f.y;
            f = __half22float2(*(__half2*)&kk.y); a1 += q0.z*f.x + q0.w*f.y;
            f = __half22float2(*(__half2*)&kk.z); a1 += q1.x*f.x + q1.y*f.y;
            f = __half22float2(*(__half2*)&kk.w); a1 += q1.z*f.x + q1.w*f.y;
            uint4 kk2 = *(const uint4*)&k2[u*4];
            f = __half22float2(*(__half2*)&kk2.x); a2 += q0.x*f.x + q0.y*f.y;
            f = __half22float2(*(__half2*)&kk2.y); a2 += q0.z*f.x + q0.w*f.y;
            f = __half22float2(*(__half2*)&kk2.z); a2 += q1.x*f.x + q1.y*f.y;
            f = __half22float2(*(__half2*)&kk2.w); a2 += q1.z*f.x + q1.w*f.y;
        }

        float l0 = a1 + Rs[(biy + i1)*HALO + bix + j1];
        float l1 = has2 ? (a2 + Rs[(biy + i2)*HALO + bix + j2]) : -1e30f;

        float mx = fmaxf(l0, l1);
        #pragma unroll
        for (int s = 16; s; s >>= 1)
            mx = fmaxf(mx, __shfl_xor_sync(0xffffffffu, mx, s));

        float p0 = __expf(l0 - mx);
        float p1 = has2 ? __expf(l1 - mx) : 0.0f;

        float sum = p0 + p1;
        #pragma unroll
        for (int s = 16; s; s >>= 1)
            sum += __shfl_xor_sync(0xffffffffu, sum, s);
        float inv = 1.0f / sum;

        Ps[w*52 + lane] = p0;
        if (has2) Ps[w*52 + 32 + lane] = p1;
        __syncwarp();

        float accx = 0.0f, accy = 0.0f;
        #pragma unroll
        for (int n = 0; n < 49; n += 2) {
            int nb = n + pair;
            float p = Ps[w*52 + nb];
            int row = robase + noff_s[nb];
            unsigned vv = Vsh[row*VSU + dpos];
            float2 vf = __half22float2(*(__half2*)&vv);
            accx += p * vf.x;
            accy += p * vf.y;
        }
        accx += __shfl_xor_sync(0xffffffffu, accx, 16);
        accy += __shfl_xor_sync(0xffffffffu, accy, 16);

        if (pair == 0) {
            int gy = qy*dil + ry;
            int gx = qx*dil + rx;
            float2 o;
            o.x = accx * inv;
            o.y = accy * inv;
            *(float2*)&g_att[((long)(b*POS) + gy*WW + gx)*C_ + h*HD + 2*dpos] = o;
        }
    }
}

// ---------------------------------------------------------------------------
extern "C" void kernel_launch(void* const* d_in, const int* in_sizes, int n_in,
                              void* d_out, int out_size)
{
    const float* x      = (const float*)d_in[0];
    const float* w_qkv  = (const float*)d_in[1];
    const float* b_qkv  = (const float*)d_in[2];
    const float* w_proj = (const float*)d_in[3];
    const float* b_proj = (const float*)d_in[4];
    const float* rpb0   = (const float*)d_in[5];
    const float* rpb1   = (const float*)d_in[6];
    float* out = (float*)d_out;

    const int smem_qkv  = 3*(128*ASTR + 16*(128+8))*4;   // 56832
    const int smem_proj = 3*(64*ASTR + 16*(64+8))*4;     // 29184

    cudaFuncSetAttribute((const void*)gemm_tf32_kernel<128,128,4>,
                         cudaFuncAttributeMaxDynamicSharedMemorySize, smem_qkv);
    cudaFuncSetAttribute((const void*)gemm_tf32_kernel<64,64,2>,
                         cudaFuncAttributeMaxDynamicSharedMemorySize, smem_proj);

    dim3 blk(256);
    gemm_tf32_kernel<128,128,4><<<dim3(6, 49), blk, smem_qkv>>>(x, w_qkv, b_qkv,
                                                                nullptr, 3*C_, 0);
    natten_kernel<<<dim3(64, NH, B_), NTHR>>>(rpb0, rpb1);
    gemm_tf32_kernel<64,64,2><<<dim3(4, 98), blk, smem_proj>>>(nullptr, w_proj, b_proj,
                                                               out, C_, 1);
}

// round 12
// speedup vs baseline: 1.0270x; 1.0270x over previous
#include <cuda_runtime.h>
#include <cuda_fp16.h>
#include <math.h>

// Problem constants
#define B_   2
#define HH   56
#define WW   56
#define C_   256
#define NH   8
#define HD   32
#define TOK  (B_*HH*WW)      // 6272
#define POS  (HH*WW)         // 3136
#define QSCALE 0.17677669529663687f

__device__ float g_q[B_*NH*POS*HD];
__device__ float g_k[B_*NH*POS*HD];
__device__ float g_v[B_*NH*POS*HD];
__device__ float g_att[TOK*C_];          // tf32-rounded by natten

// pre-rounded tf32 weights
__device__ unsigned g_wq32[C_*3*C_];
__device__ unsigned g_wp32[C_*C_];

__device__ __forceinline__ unsigned f2tf32(float f) {
    unsigned u;
    asm("cvt.rna.tf32.f32 %0, %1;" : "=r"(u) : "f"(f));
    return u;
}
__device__ __forceinline__ unsigned u2tf32(unsigned raw) {
    return f2tf32(__uint_as_float(raw));
}

// ---------------------------------------------------------------------------
// Prep: round ONLY the weights to tf32 (262144 floats).
// ---------------------------------------------------------------------------
#define WQW (C_*3*C_)    // 196608
#define WPW (C_*C_)      // 65536

__global__ void conv_w_kernel(const float* __restrict__ wq,
                              const float* __restrict__ wp)
{
    int i4 = blockIdx.x * blockDim.x + threadIdx.x;   // float4 index
    int w0 = i4 * 4;
    const float* src;
    unsigned* dst;
    int off;
    if (w0 < WQW) { src = wq; dst = g_wq32; off = w0; }
    else          { src = wp; dst = g_wp32; off = w0 - WQW; }
    float4 v = *(const float4*)&src[off];
    uint4 u;
    u.x = f2tf32(v.x); u.y = f2tf32(v.y);
    u.z = f2tf32(v.z); u.w = f2tf32(v.w);
    *(uint4*)&dst[off] = u;
}

// ---------------------------------------------------------------------------
// tf32 GEMM, cp.async 3-stage, early prefetch issue.
//   qkv : BM=128, BN=128, warps 4x2, A=x raw fp32 (frag cvt), B=g_wq32
//   proj: BM=64,  BN=64,  warps 2x4, A=g_att (pre-rounded), B=g_wp32, no cvt
// ---------------------------------------------------------------------------
#define ASTR 20
#define NKT  16

__device__ __forceinline__ void cp_async16(unsigned saddr, const void* g) {
    asm volatile("cp.async.ca.shared.global [%0], [%1], 16;"
                 :: "r"(saddr), "l"(g));
}

template<int BM, int BN, int WMW, bool CVTA>
__global__ __launch_bounds__(256) void gemm_tf32_kernel(
    const unsigned* __restrict__ A, const unsigned* __restrict__ Bw,
    const float* __restrict__ bias, float* __restrict__ Cout,
    int N, int mode)
{
    constexpr int WNW = 8 / WMW;
    constexpr int NT  = BN / (WNW * 8);
    constexpr int MT  = BM / (WMW * 16);
    constexpr int BSTR = BN + 8;
    constexpr int A_WORDS = BM * ASTR;
    constexpr int B_WORDS = 16 * BSTR;
    constexpr int STAGE_WORDS = A_WORDS + B_WORDS;
    constexpr int ALOADS = BM / 64;
    constexpr int BLOADS = (16*BN/4) / 256;

    extern __shared__ unsigned dsmem[];
    const unsigned sbase = (unsigned)__cvta_generic_to_shared(dsmem);

    const unsigned* __restrict__ Ap = A ? A : (const unsigned*)g_att;

    const int tid  = threadIdx.x;
    const int lane = tid & 31;
    const int w    = tid >> 5;
    const int wm   = w / WNW;
    const int wn   = w % WNW;
    const int g    = lane >> 2;
    const int tg   = lane & 3;

    const int row0 = blockIdx.y * BM;
    const int col0 = blockIdx.x * BN;

    const int a_r0 = tid >> 2,  a_c0 = (tid & 3) << 2;
    const int b_r0 = (BN == 128) ? (tid >> 5) : (tid >> 4);
    const int b_c0 = (BN == 128) ? ((tid & 31) << 2) : ((tid & 15) << 2);

    float c[MT][NT][4];
    #pragma unroll
    for (int mt = 0; mt < MT; mt++)
        #pragma unroll
        for (int nt = 0; nt < NT; nt++)
            #pragma unroll
            for (int i = 0; i < 4; i++)
                c[mt][nt][i] = 0.0f;

    auto issue_tile = [&](int kt, int st) {
        int k0 = kt * 16;
        unsigned ab = sbase + st*STAGE_WORDS*4;
        #pragma unroll
        for (int ld = 0; ld < ALOADS; ld++) {
            int r = a_r0 + ld*64;
            cp_async16(ab + (r*ASTR + a_c0)*4,
                       &Ap[(long)(row0 + r)*256 + k0 + a_c0]);
        }
        unsigned bb = ab + A_WORDS*4;
        #pragma unroll
        for (int ld = 0; ld < BLOADS; ld++) {
            int r = b_r0 + ld*8;
            cp_async16(bb + (r*BSTR + b_c0)*4,
                       &Bw[(long)(k0 + r)*N + col0 + b_c0]);
        }
        asm volatile("cp.async.commit_group;");
    };

    issue_tile(0, 0);
    issue_tile(1, 1);

    for (int kt = 0; kt < NKT; kt++) {
        if (kt + 1 < NKT)
            asm volatile("cp.async.wait_group 1;" ::: "memory");
        else
            asm volatile("cp.async.wait_group 0;" ::: "memory");
        __syncthreads();

        // Early prefetch: stage (kt+2)%3 was fully consumed in iter kt-1,
        // and every thread passed that compute before this barrier.
        if (kt + 2 < NKT)
            issue_tile(kt + 2, (kt + 2) % 3);

        const unsigned* As = dsmem + (kt % 3)*STAGE_WORDS;
        const unsigned* Bs = As + A_WORDS;

        #pragma unroll
        for (int kc = 0; kc < 16; kc += 8) {
            unsigned a[MT][4], bf[NT][2];
            #pragma unroll
            for (int mt = 0; mt < MT; mt++) {
                int rb = wm*(MT*16) + mt*16;
                unsigned r0 = As[(rb + g    )*ASTR + kc + tg    ];
                unsigned r1 = As[(rb + g + 8)*ASTR + kc + tg    ];
                unsigned r2 = As[(rb + g    )*ASTR + kc + tg + 4];
                unsigned r3 = As[(rb + g + 8)*ASTR + kc + tg + 4];
                if (CVTA) { r0 = u2tf32(r0); r1 = u2tf32(r1);
                            r2 = u2tf32(r2); r3 = u2tf32(r3); }
                a[mt][0] = r0; a[mt][1] = r1; a[mt][2] = r2; a[mt][3] = r3;
            }
            #pragma unroll
            for (int nt = 0; nt < NT; nt++) {
                int cb = wn*(NT*8) + nt*8;
                bf[nt][0] = Bs[(kc + tg    )*BSTR + cb + g];
                bf[nt][1] = Bs[(kc + tg + 4)*BSTR + cb + g];
            }
            #pragma unroll
            for (int mt = 0; mt < MT; mt++)
                #pragma unroll
                for (int nt = 0; nt < NT; nt++)
                    asm volatile(
                        "mma.sync.aligned.m16n8k8.row.col.f32.tf32.tf32.f32 "
                        "{%0,%1,%2,%3}, {%4,%5,%6,%7}, {%8,%9}, {%0,%1,%2,%3};"
                        : "+f"(c[mt][nt][0]), "+f"(c[mt][nt][1]),
                          "+f"(c[mt][nt][2]), "+f"(c[mt][nt][3])
                        : "r"(a[mt][0]), "r"(a[mt][1]), "r"(a[mt][2]), "r"(a[mt][3]),
                          "r"(bf[nt][0]), "r"(bf[nt][1]));
        }
    }

    // Epilogue
    #pragma unroll
    for (int mt = 0; mt < MT; mt++) {
        int r_lo = row0 + wm*(MT*16) + mt*16 + g;
        int r_hi = r_lo + 8;
        #pragma unroll
        for (int nt = 0; nt < NT; nt++) {
            int gj = col0 + wn*(NT*8) + nt*8 + 2*tg;
            float b0 = bias[gj], b1 = bias[gj+1];
            if (mode == 1) {
                Cout[(long)r_lo*N + gj    ] = c[mt][nt][0] + b0;
                Cout[(long)r_lo*N + gj + 1] = c[mt][nt][1] + b1;
                Cout[(long)r_hi*N + gj    ] = c[mt][nt][2] + b0;
                Cout[(long)r_hi*N + gj + 1] = c[mt][nt][3] + b1;
            } else {
                int t = gj >> 8;
                int h = (gj >> 5) & 7;
                int d = gj & 31;
                #pragma unroll
                for (int e = 0; e < 4; e++) {
                    int gm = (e < 2) ? r_lo : r_hi;
                    float v = c[mt][nt][e] + ((e & 1) ? b1 : b0);
                    int bb  = gm / POS;
                    int pos = gm % POS;
                    long off = ((long)(bb*NH + h)*POS + pos)*HD + d + (e & 1);
                    if (t == 0)       g_q[off] = v * QSCALE;
                    else if (t == 1)  g_k[off] = v;
                    else              g_v[off] = v;
                }
            }
        }
    }
}

// ---------------------------------------------------------------------------
// Neighborhood attention: fp16 K/V smem, fp32 Q/accum, 224 threads (7 warps,
// 7 queries per warp). Stores g_att tf32-rounded for proj's raw consumption.
// ---------------------------------------------------------------------------
#define HALO 13
#define NROW (HALO*HALO)   // 169
#define KSU  20
#define VSU  18
#define NTHR 224

__global__ __launch_bounds__(NTHR) void natten_kernel(const float* __restrict__ rpb0,
                                                      const float* __restrict__ rpb1)
{
    __shared__ alignas(16) unsigned Ksh[NROW*KSU];
    __shared__ alignas(16) unsigned Vsh[NROW*VSU];
    __shared__ alignas(16) float    Qs[49*HD];
    __shared__ alignas(16) float    Ps[7*52];
    __shared__ alignas(16) float    Rs[NROW];
    __shared__ int noff_s[52];

    const int b = blockIdx.z;
    const int h = blockIdx.y;
    const int dil = (h < 4) ? 1 : 2;
    const float* __restrict__ rpb = (h < 4) ? (rpb0 + h*NROW) : (rpb1 + (h-4)*NROW);

    int ry, rx, qy0, qx0, L;
    if (dil == 1) {
        L = 56; ry = 0; rx = 0;
        qy0 = (blockIdx.x >> 3) * 7;
        qx0 = (blockIdx.x & 7) * 7;
    } else {
        L = 28;
        int sub = blockIdx.x >> 4;
        ry = sub >> 1; rx = sub & 1;
        int ti = blockIdx.x & 15;
        qy0 = (ti >> 2) * 7;
        qx0 = (ti & 3) * 7;
    }

    int hy0 = qy0 - 3; if (hy0 < 0) hy0 = 0; if (hy0 > L - HALO) hy0 = L - HALO;
    int hx0 = qx0 - 3; if (hx0 < 0) hx0 = 0; if (hx0 > L - HALO) hx0 = L - HALO;

    const long base = ((long)(b*NH + h)) * POS * HD;
    const int tid = threadIdx.x;

    for (int item = tid; item < NROW*8; item += NTHR) {
        int t  = item >> 3;
        int c  = (item & 7) * 4;
        int iy = t / HALO, ix = t % HALO;
        int gy = (hy0 + iy)*dil + ry;
        int gx = (hx0 + ix)*dil + rx;
        long off = base + (long)(gy*WW + gx)*HD + c;
        float4 kv = *(const float4*)&g_k[off];
        __half2 k01 = __floats2half2_rn(kv.x, kv.y);
        __half2 k23 = __floats2half2_rn(kv.z, kv.w);
        uint2 ku;
        ku.x = *(unsigned*)&k01;  ku.y = *(unsigned*)&k23;
        *(uint2*)&Ksh[t*KSU + (c >> 1)] = ku;
        float4 vv = *(const float4*)&g_v[off];
        __half2 v01 = __floats2half2_rn(vv.x, vv.y);
        __half2 v23 = __floats2half2_rn(vv.z, vv.w);
        uint2 vu;
        vu.x = *(unsigned*)&v01;  vu.y = *(unsigned*)&v23;
        *(uint2*)&Vsh[t*VSU + (c >> 1)] = vu;
    }
    for (int item = tid; item < 49*8; item += NTHR) {
        int q = item >> 3;
        int c = (item & 7) * 4;
        int gy = (qy0 + q/7)*dil + ry;
        int gx = (qx0 + q%7)*dil + rx;
        *(float4*)&Qs[q*HD + c] =
            *(const float4*)&g_q[base + (long)(gy*WW + gx)*HD + c];
    }
    for (int t = tid; t < NROW; t += NTHR) Rs[t] = rpb[t];
    for (int i = tid; i < 52; i += NTHR)
        noff_s[i] = (i < 49) ? (i/7)*HALO + (i%7) : 0;
    __syncthreads();

    const int w    = tid >> 5;          // 0..6
    const int lane = tid & 31;

    if (lane < 3) Ps[w*52 + 49 + lane] = 0.0f;

    const int n1 = lane;
    const int i1 = n1 / 7, j1 = n1 % 7;
    const bool has2 = (lane < 17);
    const int n2 = 32 + lane;
    const int i2 = has2 ? n2 / 7 : 0;
    const int j2 = has2 ? n2 % 7 : 0;
    const int c1 = i1*HALO + j1;
    const int c2 = i2*HALO + j2;

    const int pair = lane >> 4;
    const int dpos = lane & 15;

    #pragma unroll
    for (int t = 0; t < 7; t++) {
        int q = w*7 + t;
        int qy = qy0 + q / 7;
        int qx = qx0 + q % 7;

        int wsy = qy - 3; if (wsy < 0) wsy = 0; if (wsy > L-7) wsy = L-7;
        int wsx = qx - 3; if (wsx < 0) wsx = 0; if (wsx > L-7) wsx = L-7;
        int oy = wsy - hy0, ox = wsx - hx0;
        int robase = oy*HALO + ox;
        int biy = wsy - qy + 6, bix = wsx - qx + 6;

        const unsigned* k1 = &Ksh[(robase + c1) * KSU];
        const unsigned* k2 = &Ksh[(robase + c2) * KSU];
        const float* qp = &Qs[q*HD];

        float a1 = 0.0f, a2 = 0.0f;
        #pragma unroll
        for (int u = 0; u < 4; u++) {
            float4 q0 = *(const float4*)&qp[u*8];
            float4 q1 = *(const float4*)&qp[u*8 + 4];
            uint4 kk = *(const uint4*)&k1[u*4];
            float2 f;
            f = __half22float2(*(__half2*)&kk.x); a1 += q0.x*f.x + q0.y*f.y;
            f = __half22float2(*(__half2*)&kk.y); a1 += q0.z*f.x + q0.w*f.y;
            f = __half22float2(*(__half2*)&kk.z); a1 += q1.x*f.x + q1.y*f.y;
            f = __half22float2(*(__half2*)&kk.w); a1 += q1.z*f.x + q1.w*f.y;
            uint4 kk2 = *(const uint4*)&k2[u*4];
            f = __half22float2(*(__half2*)&kk2.x); a2 += q0.x*f.x + q0.y*f.y;
            f = __half22float2(*(__half2*)&kk2.y); a2 += q0.z*f.x + q0.w*f.y;
            f = __half22float2(*(__half2*)&kk2.z); a2 += q1.x*f.x + q1.y*f.y;
            f = __half22float2(*(__half2*)&kk2.w); a2 += q1.z*f.x + q1.w*f.y;
        }

        float l0 = a1 + Rs[(biy + i1)*HALO + bix + j1];
        float l1 = has2 ? (a2 + Rs[(biy + i2)*HALO + bix + j2]) : -1e30f;

        float mx = fmaxf(l0, l1);
        #pragma unroll
        for (int s = 16; s; s >>= 1)
            mx = fmaxf(mx, __shfl_xor_sync(0xffffffffu, mx, s));

        float p0 = __expf(l0 - mx);
        float p1 = has2 ? __expf(l1 - mx) : 0.0f;

        float sum = p0 + p1;
        #pragma unroll
        for (int s = 16; s; s >>= 1)
            sum += __shfl_xor_sync(0xffffffffu, sum, s);
        float inv = 1.0f / sum;

        Ps[w*52 + lane] = p0;
        if (has2) Ps[w*52 + 32 + lane] = p1;
        __syncwarp();

        float accx = 0.0f, accy = 0.0f;
        #pragma unroll
        for (int n = 0; n < 49; n += 2) {
            int nb = n + pair;
            float p = Ps[w*52 + nb];
            int row = robase + noff_s[nb];
            unsigned vv = Vsh[row*VSU + dpos];
            float2 vf = __half22float2(*(__half2*)&vv);
            accx += p * vf.x;
            accy += p * vf.y;
        }
        accx += __shfl_xor_sync(0xffffffffu, accx, 16);
        accy += __shfl_xor_sync(0xffffffffu, accy, 16);

        if (pair == 0) {
            int gy = qy*dil + ry;
            int gx = qx*dil + rx;
            float2 o;
            o.x = __uint_as_float(f2tf32(accx * inv));
            o.y = __uint_as_float(f2tf32(accy * inv));
            *(float2*)&g_att[((long)(b*POS) + gy*WW + gx)*C_ + h*HD + 2*dpos] = o;
        }
    }
}

// ---------------------------------------------------------------------------
extern "C" void kernel_launch(void* const* d_in, const int* in_sizes, int n_in,
                              void* d_out, int out_size)
{
    const float* x      = (const float*)d_in[0];
    const float* w_qkv  = (const float*)d_in[1];
    const float* b_qkv  = (const float*)d_in[2];
    const float* w_proj = (const float*)d_in[3];
    const float* b_proj = (const float*)d_in[4];
    const float* rpb0   = (const float*)d_in[5];
    const float* rpb1   = (const float*)d_in[6];
    float* out = (float*)d_out;

    const int smem_qkv  = 3*(128*ASTR + 16*(128+8))*4;   // 56832
    const int smem_proj = 3*(64*ASTR + 16*(64+8))*4;     // 29184

    cudaFuncSetAttribute((const void*)gemm_tf32_kernel<128,128,4,true>,
                         cudaFuncAttributeMaxDynamicSharedMemorySize, smem_qkv);
    cudaFuncSetAttribute((const void*)gemm_tf32_kernel<64,64,2,false>,
                         cudaFuncAttributeMaxDynamicSharedMemorySize, smem_proj);

    static unsigned *p_wq32 = nullptr, *p_wp32 = nullptr;
    if (!p_wq32) {
        cudaGetSymbolAddress((void**)&p_wq32, g_wq32);
        cudaGetSymbolAddress((void**)&p_wp32, g_wp32);
    }

    conv_w_kernel<<<(WQW+WPW)/4/256, 256>>>(w_qkv, w_proj);

    dim3 blk(256);
    gemm_tf32_kernel<128,128,4,true><<<dim3(6, 49), blk, smem_qkv>>>(
        (const unsigned*)x, p_wq32, b_qkv, nullptr, 3*C_, 0);
    natten_kernel<<<dim3(64, NH, B_), NTHR>>>(rpb0, rpb1);
    gemm_tf32_kernel<64,64,2,false><<<dim3(4, 98), blk, smem_proj>>>(
        nullptr, p_wp32, b_proj, out, C_, 1);
}

// round 13
// speedup vs baseline: 1.1091x; 1.0799x over previous
#include <cuda_runtime.h>
#include <cuda_fp16.h>
#include <math.h>

// Problem constants
#define B_   2
#define HH   56
#define WW   56
#define C_   256
#define NH   8
#define HD   32
#define TOK  (B_*HH*WW)      // 6272
#define POS  (HH*WW)         // 3136
#define QSCALE 0.17677669529663687f

__device__ float g_q[B_*NH*POS*HD];
__device__ float g_k[B_*NH*POS*HD];
__device__ float g_v[B_*NH*POS*HD];
__device__ float g_att[TOK*C_];          // tf32-rounded by natten

// pre-rounded tf32 operands
__device__ unsigned g_x32[TOK*C_];
__device__ unsigned g_wq32[C_*3*C_];
__device__ unsigned g_wp32[C_*C_];

__device__ __forceinline__ unsigned f2tf32(float f) {
    unsigned u;
    asm("cvt.rna.tf32.f32 %0, %1;" : "=r"(u) : "f"(f));
    return u;
}

// ---------------------------------------------------------------------------
// Prep: round x, w_qkv, w_proj to tf32 once (R10-proven).
// ---------------------------------------------------------------------------
#define XW  (TOK*C_)
#define WQW (C_*3*C_)
#define WPW (C_*C_)
#define TOTW (XW + WQW + WPW)

__global__ void conv_kernel(const float* __restrict__ x,
                            const float* __restrict__ wq,
                            const float* __restrict__ wp)
{
    int i4 = blockIdx.x * blockDim.x + threadIdx.x;
    int n4 = TOTW / 4;
    for (; i4 < n4; i4 += gridDim.x * blockDim.x) {
        int w0 = i4 * 4;
        const float* src;
        unsigned* dst;
        int off;
        if (w0 < XW)            { src = x;  dst = g_x32;  off = w0; }
        else if (w0 < XW+WQW)   { src = wq; dst = g_wq32; off = w0 - XW; }
        else                    { src = wp; dst = g_wp32; off = w0 - XW - WQW; }
        float4 v = *(const float4*)&src[off];
        uint4 u;
        u.x = f2tf32(v.x); u.y = f2tf32(v.y);
        u.z = f2tf32(v.z); u.w = f2tf32(v.w);
        *(uint4*)&dst[off] = u;
    }
}

// ---------------------------------------------------------------------------
// tf32 GEMM, cp.async 3-stage, pre-rounded operands (no in-loop cvt).
// Template: BM x BN tile, BK, 256 threads, warps WMW x (8/WMW).
//   qkv : <128,128,16,4>  (R10-measured config)
//   proj: <64,64,32,2>    (NKT=8: half the barriers, 2x MMA per barrier)
// ---------------------------------------------------------------------------
__device__ __forceinline__ void cp_async16(unsigned saddr, const void* g) {
    asm volatile("cp.async.ca.shared.global [%0], [%1], 16;"
                 :: "r"(saddr), "l"(g));
}

template<int BM, int BN, int BK, int WMW>
__global__ __launch_bounds__(256) void gemm_tf32_kernel(
    const unsigned* __restrict__ A32, const unsigned* __restrict__ B32,
    const float* __restrict__ bias, float* __restrict__ Cout,
    int N, int mode)
{
    constexpr int WNW  = 8 / WMW;
    constexpr int NT   = BN / (WNW * 8);
    constexpr int MT   = BM / (WMW * 16);
    constexpr int ASTR = BK + 4;
    constexpr int BSTR = BN + 8;
    constexpr int A_WORDS = BM * ASTR;
    constexpr int B_WORDS = BK * BSTR;
    constexpr int STAGE_WORDS = A_WORDS + B_WORDS;
    constexpr int NKT  = 256 / BK;
    constexpr int CPRA = BK / 4;               // uint4 chunks per A row
    constexpr int CPRB = BN / 4;
    constexpr int AROWS_PASS = 256 / CPRA;
    constexpr int BROWS_PASS = 256 / CPRB;
    constexpr int ALOADS = (BM*BK/4) / 256;
    constexpr int BLOADS = (BK*BN/4) / 256;

    extern __shared__ unsigned dsmem[];
    const unsigned sbase = (unsigned)__cvta_generic_to_shared(dsmem);

    const unsigned* __restrict__ Ap = A32 ? A32 : (const unsigned*)g_att;

    const int tid  = threadIdx.x;
    const int lane = tid & 31;
    const int w    = tid >> 5;
    const int wm   = w / WNW;
    const int wn   = w % WNW;
    const int g    = lane >> 2;
    const int tg   = lane & 3;

    const int row0 = blockIdx.y * BM;
    const int col0 = blockIdx.x * BN;

    const int a_r0 = tid / CPRA,  a_c0 = (tid % CPRA) * 4;
    const int b_r0 = tid / CPRB,  b_c0 = (tid % CPRB) * 4;

    float c[MT][NT][4];
    #pragma unroll
    for (int mt = 0; mt < MT; mt++)
        #pragma unroll
        for (int nt = 0; nt < NT; nt++)
            #pragma unroll
            for (int i = 0; i < 4; i++)
                c[mt][nt][i] = 0.0f;

    auto issue_tile = [&](int kt, int st) {
        int k0 = kt * BK;
        unsigned ab = sbase + st*STAGE_WORDS*4;
        #pragma unroll
        for (int ld = 0; ld < ALOADS; ld++) {
            int r = a_r0 + ld*AROWS_PASS;
            cp_async16(ab + (r*ASTR + a_c0)*4,
                       &Ap[(long)(row0 + r)*256 + k0 + a_c0]);
        }
        unsigned bb = ab + A_WORDS*4;
        #pragma unroll
        for (int ld = 0; ld < BLOADS; ld++) {
            int r = b_r0 + ld*BROWS_PASS;
            cp_async16(bb + (r*BSTR + b_c0)*4,
                       &B32[(long)(k0 + r)*N + col0 + b_c0]);
        }
        asm volatile("cp.async.commit_group;");
    };

    issue_tile(0, 0);
    issue_tile(1, 1);

    for (int kt = 0; kt < NKT; kt++) {
        if (kt + 1 < NKT)
            asm volatile("cp.async.wait_group 1;" ::: "memory");
        else
            asm volatile("cp.async.wait_group 0;" ::: "memory");
        __syncthreads();

        const unsigned* As = dsmem + (kt % 3)*STAGE_WORDS;
        const unsigned* Bs = As + A_WORDS;

        #pragma unroll
        for (int kc = 0; kc < BK; kc += 8) {
            unsigned a[MT][4], bf[NT][2];
            #pragma unroll
            for (int mt = 0; mt < MT; mt++) {
                int rb = wm*(MT*16) + mt*16;
                a[mt][0] = As[(rb + g    )*ASTR + kc + tg    ];
                a[mt][1] = As[(rb + g + 8)*ASTR + kc + tg    ];
                a[mt][2] = As[(rb + g    )*ASTR + kc + tg + 4];
                a[mt][3] = As[(rb + g + 8)*ASTR + kc + tg + 4];
            }
            #pragma unroll
            for (int nt = 0; nt < NT; nt++) {
                int cb = wn*(NT*8) + nt*8;
                bf[nt][0] = Bs[(kc + tg    )*BSTR + cb + g];
                bf[nt][1] = Bs[(kc + tg + 4)*BSTR + cb + g];
            }
            #pragma unroll
            for (int mt = 0; mt < MT; mt++)
                #pragma unroll
                for (int nt = 0; nt < NT; nt++)
                    asm volatile(
                        "mma.sync.aligned.m16n8k8.row.col.f32.tf32.tf32.f32 "
                        "{%0,%1,%2,%3}, {%4,%5,%6,%7}, {%8,%9}, {%0,%1,%2,%3};"
                        : "+f"(c[mt][nt][0]), "+f"(c[mt][nt][1]),
                          "+f"(c[mt][nt][2]), "+f"(c[mt][nt][3])
                        : "r"(a[mt][0]), "r"(a[mt][1]), "r"(a[mt][2]), "r"(a[mt][3]),
                          "r"(bf[nt][0]), "r"(bf[nt][1]));
        }

        if (kt + 2 < NKT)
            issue_tile(kt + 2, (kt + 2) % 3);
    }

    // Epilogue
    #pragma unroll
    for (int mt = 0; mt < MT; mt++) {
        int r_lo = row0 + wm*(MT*16) + mt*16 + g;
        int r_hi = r_lo + 8;
        #pragma unroll
        for (int nt = 0; nt < NT; nt++) {
            int gj = col0 + wn*(NT*8) + nt*8 + 2*tg;
            float b0 = bias[gj], b1 = bias[gj+1];
            if (mode == 1) {
                Cout[(long)r_lo*N + gj    ] = c[mt][nt][0] + b0;
                Cout[(long)r_lo*N + gj + 1] = c[mt][nt][1] + b1;
                Cout[(long)r_hi*N + gj    ] = c[mt][nt][2] + b0;
                Cout[(long)r_hi*N + gj + 1] = c[mt][nt][3] + b1;
            } else {
                int t = gj >> 8;
                int h = (gj >> 5) & 7;
                int d = gj & 31;
                #pragma unroll
                for (int e = 0; e < 4; e++) {
                    int gm = (e < 2) ? r_lo : r_hi;
                    float v = c[mt][nt][e] + ((e & 1) ? b1 : b0);
                    int bb  = gm / POS;
                    int pos = gm % POS;
                    long off = ((long)(bb*NH + h)*POS + pos)*HD + d + (e & 1);
                    if (t == 0)       g_q[off] = v * QSCALE;
                    else if (t == 1)  g_k[off] = v;
                    else              g_v[off] = v;
                }
            }
        }
    }
}

// ---------------------------------------------------------------------------
// Neighborhood attention: fp16 K/V smem, fp32 Q/accum, 448 threads (14 warps,
// ≤4 query rounds). Stores g_att tf32-rounded for proj's raw consumption.
// ---------------------------------------------------------------------------
#define HALO 13
#define NROW (HALO*HALO)   // 169
#define KSU  20
#define VSU  18
#define NTHR 448

__global__ __launch_bounds__(NTHR) void natten_kernel(const float* __restrict__ rpb0,
                                                      const float* __restrict__ rpb1)
{
    __shared__ alignas(16) unsigned Ksh[NROW*KSU];
    __shared__ alignas(16) unsigned Vsh[NROW*VSU];
    __shared__ alignas(16) float    Qs[49*HD];
    __shared__ alignas(16) float    Ps[14*52];
    __shared__ alignas(16) float    Rs[NROW];
    __shared__ int noff_s[52];

    const int b = blockIdx.z;
    const int h = blockIdx.y;
    const int dil = (h < 4) ? 1 : 2;
    const float* __restrict__ rpb = (h < 4) ? (rpb0 + h*NROW) : (rpb1 + (h-4)*NROW);

    int ry, rx, qy0, qx0, L;
    if (dil == 1) {
        L = 56; ry = 0; rx = 0;
        qy0 = (blockIdx.x >> 3) * 7;
        qx0 = (blockIdx.x & 7) * 7;
    } else {
        L = 28;
        int sub = blockIdx.x >> 4;
        ry = sub >> 1; rx = sub & 1;
        int ti = blockIdx.x & 15;
        qy0 = (ti >> 2) * 7;
        qx0 = (ti & 3) * 7;
    }

    int hy0 = qy0 - 3; if (hy0 < 0) hy0 = 0; if (hy0 > L - HALO) hy0 = L - HALO;
    int hx0 = qx0 - 3; if (hx0 < 0) hx0 = 0; if (hx0 > L - HALO) hx0 = L - HALO;

    const long base = ((long)(b*NH + h)) * POS * HD;
    const int tid = threadIdx.x;

    for (int item = tid; item < NROW*8; item += NTHR) {
        int t  = item >> 3;
        int c  = (item & 7) * 4;
        int iy = t / HALO, ix = t % HALO;
        int gy = (hy0 + iy)*dil + ry;
        int gx = (hx0 + ix)*dil + rx;
        long off = base + (long)(gy*WW + gx)*HD + c;
        float4 kv = *(const float4*)&g_k[off];
        __half2 k01 = __floats2half2_rn(kv.x, kv.y);
        __half2 k23 = __floats2half2_rn(kv.z, kv.w);
        uint2 ku;
        ku.x = *(unsigned*)&k01;  ku.y = *(unsigned*)&k23;
        *(uint2*)&Ksh[t*KSU + (c >> 1)] = ku;
        float4 vv = *(const float4*)&g_v[off];
        __half2 v01 = __floats2half2_rn(vv.x, vv.y);
        __half2 v23 = __floats2half2_rn(vv.z, vv.w);
        uint2 vu;
        vu.x = *(unsigned*)&v01;  vu.y = *(unsigned*)&v23;
        *(uint2*)&Vsh[t*VSU + (c >> 1)] = vu;
    }
    for (int item = tid; item < 49*8; item += NTHR) {
        int q = item >> 3;
        int c = (item & 7) * 4;
        int gy = (qy0 + q/7)*dil + ry;
        int gx = (qx0 + q%7)*dil + rx;
        *(float4*)&Qs[q*HD + c] =
            *(const float4*)&g_q[base + (long)(gy*WW + gx)*HD + c];
    }
    for (int t = tid; t < NROW; t += NTHR) Rs[t] = rpb[t];
    for (int i = tid; i < 52; i += NTHR)
        noff_s[i] = (i < 49) ? (i/7)*HALO + (i%7) : 0;
    __syncthreads();

    const int w    = tid >> 5;          // 0..13
    const int lane = tid & 31;

    if (lane < 3) Ps[w*52 + 49 + lane] = 0.0f;

    const int n1 = lane;
    const int i1 = n1 / 7, j1 = n1 % 7;
    const bool has2 = (lane < 17);
    const int n2 = 32 + lane;
    const int i2 = has2 ? n2 / 7 : 0;
    const int j2 = has2 ? n2 % 7 : 0;
    const int c1 = i1*HALO + j1;
    const int c2 = i2*HALO + j2;

    const int pair = lane >> 4;
    const int dpos = lane & 15;

    #pragma unroll
    for (int t = 0; t < 4; t++) {
        int q = w + 14*t;
        if (q >= 49) break;
        int qy = qy0 + q / 7;
        int qx = qx0 + q % 7;

        int wsy = qy - 3; if (wsy < 0) wsy = 0; if (wsy > L-7) wsy = L-7;
        int wsx = qx - 3; if (wsx < 0) wsx = 0; if (wsx > L-7) wsx = L-7;
        int oy = wsy - hy0, ox = wsx - hx0;
        int robase = oy*HALO + ox;
        int biy = wsy - qy + 6, bix = wsx - qx + 6;

        const unsigned* k1 = &Ksh[(robase + c1) * KSU];
        const unsigned* k2 = &Ksh[(robase + c2) * KSU];
        const float* qp = &Qs[q*HD];

        float a1 = 0.0f, a2 = 0.0f;
        #pragma unroll
        for (int u = 0; u < 4; u++) {
            float4 q0 = *(const float4*)&qp[u*8];
            float4 q1 = *(const float4*)&qp[u*8 + 4];
            uint4 kk = *(const uint4*)&k1[u*4];
            float2 f;
            f = __half22float2(*(__half2*)&kk.x); a1 += q0.x*f.x + q0.y*f.y;
            f = __half22float2(*(__half2*)&kk.y); a1 += q0.z*f.x + q0.w*f.y;
            f = __half22float2(*(__half2*)&kk.z); a1 += q1.x*f.x + q1.y*f.y;
            f = __half22float2(*(__half2*)&kk.w); a1 += q1.z*f.x + q1.w*f.y;
            uint4 kk2 = *(const uint4*)&k2[u*4];
            f = __half22float2(*(__half2*)&kk2.x); a2 += q0.x*f.x + q0.y*f.y;
            f = __half22float2(*(__half2*)&kk2.y); a2 += q0.z*f.x + q0.w*f.y;
            f = __half22float2(*(__half2*)&kk2.z); a2 += q1.x*f.x + q1.y*f.y;
            f = __half22float2(*(__half2*)&kk2.w); a2 += q1.z*f.x + q1.w*f.y;
        }

        float l0 = a1 + Rs[(biy + i1)*HALO + bix + j1];
        float l1 = has2 ? (a2 + Rs[(biy + i2)*HALO + bix + j2]) : -1e30f;

        float mx = fmaxf(l0, l1);
        #pragma unroll
        for (int s = 16; s; s >>= 1)
            mx = fmaxf(mx, __shfl_xor_sync(0xffffffffu, mx, s));

        float p0 = __expf(l0 - mx);
        float p1 = has2 ? __expf(l1 - mx) : 0.0f;

        float sum = p0 + p1;
        #pragma unroll
        for (int s = 16; s; s >>= 1)
            sum += __shfl_xor_sync(0xffffffffu, sum, s);
        float inv = 1.0f / sum;

        Ps[w*52 + lane] = p0;
        if (has2) Ps[w*52 + 32 + lane] = p1;
        __syncwarp();

        float accx = 0.0f, accy = 0.0f;
        #pragma unroll
        for (int n = 0; n < 49; n += 2) {
            int nb = n + pair;
            float p = Ps[w*52 + nb];
            int row = robase + noff_s[nb];
            unsigned vv = Vsh[row*VSU + dpos];
            float2 vf = __half22float2(*(__half2*)&vv);
            accx += p * vf.x;
            accy += p * vf.y;
        }
        accx += __shfl_xor_sync(0xffffffffu, accx, 16);
        accy += __shfl_xor_sync(0xffffffffu, accy, 16);

        if (pair == 0) {
            int gy = qy*dil + ry;
            int gx = qx*dil + rx;
            float2 o;
            o.x = __uint_as_float(f2tf32(accx * inv));
            o.y = __uint_as_float(f2tf32(accy * inv));
            *(float2*)&g_att[((long)(b*POS) + gy*WW + gx)*C_ + h*HD + 2*dpos] = o;
        }
    }
}

// ---------------------------------------------------------------------------
extern "C" void kernel_launch(void* const* d_in, const int* in_sizes, int n_in,
                              void* d_out, int out_size)
{
    const float* x      = (const float*)d_in[0];
    const float* w_qkv  = (const float*)d_in[1];
    const float* b_qkv  = (const float*)d_in[2];
    const float* w_proj = (const float*)d_in[3];
    const float* b_proj = (const float*)d_in[4];
    const float* rpb0   = (const float*)d_in[5];
    const float* rpb1   = (const float*)d_in[6];
    float* out = (float*)d_out;

    const int smem_qkv  = 3*(128*(16+4) + 16*(128+8))*4;  // 56832
    const int smem_proj = 3*(64*(32+4)  + 32*(64+8))*4;   // 55296

    cudaFuncSetAttribute((const void*)gemm_tf32_kernel<128,128,16,4>,
                         cudaFuncAttributeMaxDynamicSharedMemorySize, smem_qkv);
    cudaFuncSetAttribute((const void*)gemm_tf32_kernel<64,64,32,2>,
                         cudaFuncAttributeMaxDynamicSharedMemorySize, smem_proj);

    static unsigned *p_x32 = nullptr, *p_wq32 = nullptr, *p_wp32 = nullptr;
    if (!p_x32) {
        cudaGetSymbolAddress((void**)&p_x32,  g_x32);
        cudaGetSymbolAddress((void**)&p_wq32, g_wq32);
        cudaGetSymbolAddress((void**)&p_wp32, g_wp32);
    }

    conv_kernel<<<456, 256>>>(x, w_qkv, w_proj);

    dim3 blk(256);
    gemm_tf32_kernel<128,128,16,4><<<dim3(6, 49), blk, smem_qkv>>>(
        p_x32, p_wq32, b_qkv, nullptr, 3*C_, 0);
    natten_kernel<<<dim3(64, NH, B_), NTHR>>>(rpb0, rpb1);
    gemm_tf32_kernel<64,64,32,2><<<dim3(4, 98), blk, smem_proj>>>(
        nullptr, p_wp32, b_proj, out, C_, 1);
}